// round 12
// baseline (speedup 1.0000x reference)
#include <cuda_runtime.h>
#include <cuda_bf16.h>
#include <math.h>

#define BATCH 4
#define DIMC  384
#define NTOK  2304      // 48*48
#define NHEAD 8
#define DEPTH 48
#define QKVD  1152
#define LN_EPS 1e-5f
#define BH    (BATCH*NHEAD)
#define SM_SHIFT 40.0f

// ---------------- scratch (no allocations allowed) -------------------------
__device__ __nv_bfloat16 g_xh [BATCH*NTOK*DIMC], g_xl [BATCH*NTOK*DIMC];
__device__ __nv_bfloat16 g_ah [BATCH*NTOK*DIMC], g_al [BATCH*NTOK*DIMC];
__device__ __nv_bfloat16 g_wqh[QKVD*DIMC],       g_wql[QKVD*DIMC];
__device__ __nv_bfloat16 g_woh[DIMC*DIMC],       g_wol[DIMC*DIMC];
__device__ __nv_bfloat16 g_qhi[BH*NTOK*DEPTH], g_qlo[BH*NTOK*DEPTH];
__device__ __nv_bfloat16 g_khi[BH*NTOK*DEPTH], g_klo[BH*NTOK*DEPTH];
__device__ __nv_bfloat16 g_vthi[BH*DEPTH*NTOK], g_vtlo[BH*DEPTH*NTOK];

__device__ __forceinline__ void mma16816(float* d, const unsigned* a, unsigned b0, unsigned b1) {
    asm volatile(
        "mma.sync.aligned.m16n8k16.row.col.f32.bf16.bf16.f32 "
        "{%0,%1,%2,%3},{%4,%5,%6,%7},{%8,%9},{%0,%1,%2,%3};"
        : "+f"(d[0]), "+f"(d[1]), "+f"(d[2]), "+f"(d[3])
        : "r"(a[0]), "r"(a[1]), "r"(a[2]), "r"(a[3]), "r"(b0), "r"(b1));
}

__device__ __forceinline__ void ldmx4(unsigned& r0, unsigned& r1, unsigned& r2, unsigned& r3,
                                      unsigned addr) {
    asm volatile("ldmatrix.sync.aligned.m8n8.x4.shared.b16 {%0,%1,%2,%3}, [%4];"
        : "=r"(r0), "=r"(r1), "=r"(r2), "=r"(r3) : "r"(addr));
}

__device__ __forceinline__ float ex2(float x) {
    float y;
    asm("ex2.approx.ftz.f32 %0, %1;" : "=f"(y) : "f"(x));
    return y;
}

// packed split: (p0,p1) -> hi bf16x2 (p0 lower), lo bf16x2 residuals
__device__ __forceinline__ void split2(float p0, float p1, unsigned& hi, unsigned& lo) {
    unsigned hbits;
    asm("cvt.rn.bf16x2.f32 %0, %1, %2;" : "=r"(hbits) : "f"(p1), "f"(p0));
    float h0 = __uint_as_float(hbits << 16);
    float h1 = __uint_as_float(hbits & 0xFFFF0000u);
    unsigned lbits;
    asm("cvt.rn.bf16x2.f32 %0, %1, %2;" : "=r"(lbits) : "f"(p1 - h1), "f"(p0 - h0));
    hi = hbits; lo = lbits;
}

__device__ __forceinline__ void cpasync16(unsigned dst, const void* src) {
    asm volatile("cp.async.cg.shared.global [%0], [%1], 16;" :: "r"(dst), "l"(src));
}
__device__ __forceinline__ unsigned smem_u32(const void* p) {
    unsigned a;
    asm("{ .reg .u64 t; cvta.to.shared.u64 t, %1; cvt.u32.u64 %0, t; }" : "=r"(a) : "l"(p));
    return a;
}

// attn smem stage layout (bytes)
#define ST_KH 0
#define ST_KL 7168
#define ST_VH 14336
#define ST_VL 21248
#define ST_SZ 28160

// gemm smem stage layout (32-bit words)
#define GA_H 0
#define GA_L 2560
#define GB_H 5120
#define GB_L 6400
#define G_STW 7680
#define G_STB (G_STW*4)
#define G_SMEM (2*G_STB)

// ---------------------------------------------------------------------------
__global__ void split_w(const float* __restrict__ wq, const float* __restrict__ wo) {
    int i = blockIdx.x*256 + threadIdx.x;
    if (i < QKVD*DIMC) {
        float x = wq[i];
        __nv_bfloat16 hi = __float2bfloat16_rn(x);
        g_wqh[i] = hi; g_wql[i] = __float2bfloat16_rn(x - __bfloat162float(hi));
    }
    if (i < DIMC*DIMC) {
        float x = wo[i];
        __nv_bfloat16 hi = __float2bfloat16_rn(x);
        g_woh[i] = hi; g_wol[i] = __float2bfloat16_rn(x - __bfloat162float(hi));
    }
}

// ---------------------------------------------------------------------------
// 1) LayerNorm, coalesced; register accumulation; smem-transposed writes.
// ---------------------------------------------------------------------------
__global__ void __launch_bounds__(256) ln_kernel(const float* __restrict__ feat,
                          const float* __restrict__ gamma,
                          const float* __restrict__ beta) {
    __shared__ float ps[4][64], ps2[4][64];
    __shared__ float s_mean[64], s_rstd[64];
    __shared__ __nv_bfloat16 tbh[64][66], tbl[64][66];

    int n0 = blockIdx.x * 64, b = blockIdx.y;
    int t = threadIdx.x;
    int nj = t & 63, ci4 = t >> 6;
    const float* fb = feat + (size_t)b*DIMC*NTOK + n0;

    float s = 0.f, s2 = 0.f;
    for (int c = ci4; c < DIMC; c += 4) {
        float v = fb[(size_t)c*NTOK + nj];
        s += v; s2 += v*v;
    }
    ps[ci4][nj] = s; ps2[ci4][nj] = s2;
    __syncthreads();
    if (t < 64) {
        float ts  = ps[0][t] + ps[1][t] + ps[2][t] + ps[3][t];
        float ts2 = ps2[0][t] + ps2[1][t] + ps2[2][t] + ps2[3][t];
        float mu  = ts * (1.f/DIMC);
        float var = ts2 * (1.f/DIMC) - mu*mu;
        s_mean[t] = mu;
        s_rstd[t] = rsqrtf(var + LN_EPS);
    }
    __syncthreads();

    float mu = s_mean[nj], rs = s_rstd[nj];

    for (int c0 = 0; c0 < DIMC; c0 += 64) {
        #pragma unroll
        for (int cc = 0; cc < 16; cc++) {
            int cl = cc*4 + ci4;
            int c = c0 + cl;
            float v = fb[(size_t)c*NTOK + nj];
            float x = (v - mu) * rs * gamma[c] + beta[c];
            __nv_bfloat16 hi = __float2bfloat16_rn(x);
            tbh[nj][cl] = hi;
            tbl[nj][cl] = __float2bfloat16_rn(x - __bfloat162float(hi));
        }
        __syncthreads();
        #pragma unroll
        for (int i = t; i < 64*64; i += 256) {
            int nl = i >> 6, cl = i & 63;
            size_t dst = ((size_t)(b*NTOK + n0 + nl))*DIMC + c0 + cl;
            g_xh[dst] = tbh[nl][cl];
            g_xl[dst] = tbl[nl][cl];
        }
        __syncthreads();
    }
}

// ---------------------------------------------------------------------------
// Tensor-core GEMM mainloop, cp.async double-buffered; term-major MMA order.
// ---------------------------------------------------------------------------
__device__ __forceinline__ void gemm_mainloop(
        char* dsm,
        const unsigned* Agh, const unsigned* Agl,
        const unsigned* Bgh, const unsigned* Bgl,
        int tid, int mw, int nw, int g, int tig,
        float acc[2][4][4]) {
    unsigned sbase = smem_u32(dsm);
    unsigned* smw = (unsigned*)dsm;

    auto loadc = [&](int kcw, int st) {
        unsigned base = sbase + st*G_STB;
        #pragma unroll 2
        for (int i = tid; i < 512; i += 256) {
            int r = i >> 2, c4 = (i & 3) * 4;
            cpasync16(base + (GA_H + r*20 + c4)*4, Agh + r*192 + kcw + c4);
            cpasync16(base + (GA_L + r*20 + c4)*4, Agl + r*192 + kcw + c4);
        }
        for (int i = tid; i < 256; i += 256) {
            int r = i >> 2, c4 = (i & 3) * 4;
            cpasync16(base + (GB_H + r*20 + c4)*4, Bgh + r*192 + kcw + c4);
            cpasync16(base + (GB_L + r*20 + c4)*4, Bgl + r*192 + kcw + c4);
        }
        asm volatile("cp.async.commit_group;");
    };

    loadc(0, 0);
    for (int t = 0; t < 12; t++) {
        int st = t & 1;
        asm volatile("cp.async.wait_group 0;" ::: "memory");
        __syncthreads();
        if (t + 1 < 12) loadc((t+1)*16, st ^ 1);

        const unsigned* Ah = smw + st*G_STW + GA_H;
        const unsigned* Al = smw + st*G_STW + GA_L;
        const unsigned* Bh = smw + st*G_STW + GB_H;
        const unsigned* Bl = smw + st*G_STW + GB_L;

        #pragma unroll
        for (int ks = 0; ks < 2; ks++) {
            unsigned ah[2][4], al[2][4], bh[4][2], bl[4][2];
            #pragma unroll
            for (int mi = 0; mi < 2; mi++) {
                int r = mw*32 + mi*16 + g;
                ah[mi][0] = Ah[r*20     + ks*8 + tig];
                ah[mi][1] = Ah[(r+8)*20 + ks*8 + tig];
                ah[mi][2] = Ah[r*20     + ks*8 + tig + 4];
                ah[mi][3] = Ah[(r+8)*20 + ks*8 + tig + 4];
                al[mi][0] = Al[r*20     + ks*8 + tig];
                al[mi][1] = Al[(r+8)*20 + ks*8 + tig];
                al[mi][2] = Al[r*20     + ks*8 + tig + 4];
                al[mi][3] = Al[(r+8)*20 + ks*8 + tig + 4];
            }
            #pragma unroll
            for (int ni = 0; ni < 4; ni++) {
                int n = nw*32 + ni*8 + g;
                bh[ni][0] = Bh[n*20 + ks*8 + tig];
                bh[ni][1] = Bh[n*20 + ks*8 + tig + 4];
                bl[ni][0] = Bl[n*20 + ks*8 + tig];
                bl[ni][1] = Bl[n*20 + ks*8 + tig + 4];
            }
            #pragma unroll
            for (int mi = 0; mi < 2; mi++)
                #pragma unroll
                for (int ni = 0; ni < 4; ni++)
                    mma16816(acc[mi][ni], ah[mi], bh[ni][0], bh[ni][1]);
            #pragma unroll
            for (int mi = 0; mi < 2; mi++)
                #pragma unroll
                for (int ni = 0; ni < 4; ni++)
                    mma16816(acc[mi][ni], ah[mi], bl[ni][0], bl[ni][1]);
            #pragma unroll
            for (int mi = 0; mi < 2; mi++)
                #pragma unroll
                for (int ni = 0; ni < 4; ni++)
                    mma16816(acc[mi][ni], al[mi], bh[ni][0], bh[ni][1]);
        }
    }
}

// ---------------------------------------------------------------------------
// 2) QKV projection GEMM; q/k direct scatter, V transposed through smem.
// ---------------------------------------------------------------------------
__global__ void __launch_bounds__(256) qkv_mma() {
    extern __shared__ char dsm[];
    int m0 = blockIdx.y * 128, d0 = blockIdx.x * 64;
    int tid = threadIdx.x, w = tid >> 5, lane = tid & 31;
    int g = lane >> 2, tig = lane & 3;
    int mw = w >> 1, nw = w & 1;

    float acc[2][4][4] = {};
    gemm_mainloop(dsm,
        (const unsigned*)g_xh + (size_t)m0*192, (const unsigned*)g_xl + (size_t)m0*192,
        (const unsigned*)g_wqh + (size_t)d0*192, (const unsigned*)g_wql + (size_t)d0*192,
        tid, mw, nw, g, tig, acc);

    int which = d0 / DIMC;
    int r0 = d0 - which*DIMC;
    int bb = m0 / NTOK, n0 = m0 - bb*NTOK;

    if (which < 2) {
        #pragma unroll
        for (int mi = 0; mi < 2; mi++) {
            #pragma unroll
            for (int rr = 0; rr < 2; rr++) {
                int n = n0 + mw*32 + mi*16 + g + rr*8;
                #pragma unroll
                for (int ni = 0; ni < 4; ni++) {
                    int d = r0 + nw*32 + ni*8 + 2*tig;
                    int h = d / DEPTH, dd = d - h*DEPTH;
                    int bhI = bb*NHEAD + h;
                    unsigned hi, lo;
                    split2(acc[mi][ni][rr*2], acc[mi][ni][rr*2+1], hi, lo);
                    size_t idx = ((size_t)bhI*NTOK + n)*DEPTH + dd;
                    if (which == 0) { *(unsigned*)(g_qhi+idx) = hi; *(unsigned*)(g_qlo+idx) = lo; }
                    else            { *(unsigned*)(g_khi+idx) = hi; *(unsigned*)(g_klo+idx) = lo; }
                }
            }
        }
    } else {
        __syncthreads();
        __nv_bfloat16* th = (__nv_bfloat16*)dsm;           // [64][130]
        __nv_bfloat16* tl = th + 64*130;
        #pragma unroll
        for (int mi = 0; mi < 2; mi++)
            #pragma unroll
            for (int rr = 0; rr < 2; rr++) {
                int ml = mw*32 + mi*16 + g + rr*8;
                #pragma unroll
                for (int ni = 0; ni < 4; ni++)
                    #pragma unroll
                    for (int jj = 0; jj < 2; jj++) {
                        int dl = nw*32 + ni*8 + 2*tig + jj;
                        float x = acc[mi][ni][rr*2 + jj];
                        __nv_bfloat16 hi = __float2bfloat16_rn(x);
                        th[dl*130 + ml] = hi;
                        tl[dl*130 + ml] = __float2bfloat16_rn(x - __bfloat162float(hi));
                    }
            }
        __syncthreads();
        #pragma unroll
        for (int i = tid; i < 64*128; i += 256) {
            int dl = i >> 7, n = i & 127;
            int rg = r0 + dl;
            int h = rg / DEPTH, dd = rg - h*DEPTH;
            size_t idx = ((size_t)(bb*NHEAD + h)*DEPTH + dd)*NTOK + n0 + n;
            g_vthi[idx] = th[dl*130 + n];
            g_vtlo[idx] = tl[dl*130 + n];
        }
    }
}

// ---------------------------------------------------------------------------
// 3) Tensor-core flash attention; 256 threads / 128 queries per block;
//    ldmatrix.x4 fragment loads; batched ex2.approx softmax; term-major MMAs.
// ---------------------------------------------------------------------------
__global__ void __launch_bounds__(256, 2) attn_mma(const float* __restrict__ tau) {
    extern __shared__ char dsm[];

    int qc = blockIdx.x, h = blockIdx.y, b = blockIdx.z;
    int bh = b*NHEAD + h;
    int tid = threadIdx.x, w = tid >> 5, lane = tid & 31;
    int g = lane >> 2, tig = lane & 3;
    float scale2 = expf(tau[h]) * 1.44269504088896f;
    int m0 = qc*128 + w*16;

    const char* Kh_src = (const char*)(g_khi + (size_t)bh*NTOK*DEPTH);
    const char* Kl_src = (const char*)(g_klo + (size_t)bh*NTOK*DEPTH);
    const char* Vh_src = (const char*)(g_vthi + (size_t)bh*DEPTH*NTOK);
    const char* Vl_src = (const char*)(g_vtlo + (size_t)bh*DEPTH*NTOK);
    unsigned sbase = smem_u32(dsm);

    // ldmatrix per-lane offsets: K rows stride 112B (x4: m0/m1 = nt k-lo/k-hi,
    // m2/m3 = nt+1); V rows stride 144B.
    unsigned lK = (lane & 7)*112 + ((lane >> 3) & 1)*16 + (lane >> 4)*896;
    unsigned lV = (lane & 7)*144 + ((lane >> 3) & 1)*16 + (lane >> 4)*1152;

    const __nv_bfloat16* qh = g_qhi + (size_t)bh*NTOK*DEPTH;
    const __nv_bfloat16* ql = g_qlo + (size_t)bh*NTOK*DEPTH;
    unsigned aqh[3][4], aql[3][4];
    #pragma unroll
    for (int ks = 0; ks < 3; ks++) {
        int c0 = ks*16 + 2*tig;
        aqh[ks][0] = *(const unsigned*)(qh + (size_t)(m0+g  )*DEPTH + c0);
        aqh[ks][1] = *(const unsigned*)(qh + (size_t)(m0+g+8)*DEPTH + c0);
        aqh[ks][2] = *(const unsigned*)(qh + (size_t)(m0+g  )*DEPTH + c0 + 8);
        aqh[ks][3] = *(const unsigned*)(qh + (size_t)(m0+g+8)*DEPTH + c0 + 8);
        aql[ks][0] = *(const unsigned*)(ql + (size_t)(m0+g  )*DEPTH + c0);
        aql[ks][1] = *(const unsigned*)(ql + (size_t)(m0+g+8)*DEPTH + c0);
        aql[ks][2] = *(const unsigned*)(ql + (size_t)(m0+g  )*DEPTH + c0 + 8);
        aql[ks][3] = *(const unsigned*)(ql + (size_t)(m0+g+8)*DEPTH + c0 + 8);
    }

    float o[6][4] = {};
    float lp[2] = {0.f, 0.f};

    auto load_tile = [&](int j0, int st) {
        unsigned base = sbase + st*ST_SZ;
        for (int i = tid; i < 384; i += 256) {
            int row = i / 6, c = i % 6;
            size_t src = (size_t)(j0 + row)*96 + c*16;
            cpasync16(base + ST_KH + row*112 + c*16, Kh_src + src);
            cpasync16(base + ST_KL + row*112 + c*16, Kl_src + src);
        }
        for (int i = tid; i < 384; i += 256) {
            int row = i / 8, c = i % 8;
            size_t src = ((size_t)row*NTOK + j0)*2 + c*16;
            cpasync16(base + ST_VH + row*144 + c*16, Vh_src + src);
            cpasync16(base + ST_VL + row*144 + c*16, Vl_src + src);
        }
        asm volatile("cp.async.commit_group;");
    };

    load_tile(0, 0);

    for (int t = 0; t < NTOK/64; t++) {
        int st = t & 1;
        asm volatile("cp.async.wait_group 0;" ::: "memory");
        __syncthreads();
        if (t + 1 < NTOK/64) load_tile((t+1)*64, st ^ 1);

        unsigned KhA = sbase + st*ST_SZ + ST_KH;
        unsigned KlA = sbase + st*ST_SZ + ST_KL;
        unsigned VhA = sbase + st*ST_SZ + ST_VH;
        unsigned VlA = sbase + st*ST_SZ + ST_VL;

        // ---- S = Q K^T: groups of 4 accumulators, ldmatrix.x4 loads
        float s[8][4];
        #pragma unroll
        for (int nt = 0; nt < 8; nt++) { s[nt][0]=0.f; s[nt][1]=0.f; s[nt][2]=0.f; s[nt][3]=0.f; }
        #pragma unroll
        for (int ks = 0; ks < 3; ks++) {
            #pragma unroll
            for (int h4 = 0; h4 < 8; h4 += 4) {
                unsigned kb0[4], kb1[4], kl0[4], kl1[4];
                unsigned bhA = KhA + h4*896 + ks*32 + lK;
                unsigned blA = KlA + h4*896 + ks*32 + lK;
                ldmx4(kb0[0], kb1[0], kb0[1], kb1[1], bhA);
                ldmx4(kb0[2], kb1[2], kb0[3], kb1[3], bhA + 2*896);
                ldmx4(kl0[0], kl1[0], kl0[1], kl1[1], blA);
                ldmx4(kl0[2], kl1[2], kl0[3], kl1[3], blA + 2*896);
                #pragma unroll
                for (int j = 0; j < 4; j++) mma16816(s[h4+j], aqh[ks], kb0[j], kb1[j]);
                #pragma unroll
                for (int j = 0; j < 4; j++) mma16816(s[h4+j], aqh[ks], kl0[j], kl1[j]);
                #pragma unroll
                for (int j = 0; j < 4; j++) mma16816(s[h4+j], aql[ks], kb0[j], kb1[j]);
            }
        }

        // ---- P = ex2(s*scale2 - SHIFT): 32 independent MUFUs, then splits
        unsigned Ph0[8], Ph1[8], Pl0[8], Pl1[8];
        #pragma unroll
        for (int nt = 0; nt < 8; nt++) {
            float p0 = ex2(fmaf(s[nt][0], scale2, -SM_SHIFT));
            float p1 = ex2(fmaf(s[nt][1], scale2, -SM_SHIFT));
            float p2 = ex2(fmaf(s[nt][2], scale2, -SM_SHIFT));
            float p3 = ex2(fmaf(s[nt][3], scale2, -SM_SHIFT));
            lp[0] += p0 + p1; lp[1] += p2 + p3;
            split2(p0, p1, Ph0[nt], Pl0[nt]);
            split2(p2, p3, Ph1[nt], Pl1[nt]);
        }

        // ---- O += P V: ksj-outer, ldmatrix.x4 loads, term-major MMAs
        #pragma unroll
        for (int ksj = 0; ksj < 4; ksj++) {
            unsigned vh0[6], vh1[6], vl0[6], vl1[6];
            unsigned bvh = VhA + ksj*32 + lV;
            unsigned bvl = VlA + ksj*32 + lV;
            ldmx4(vh0[0], vh1[0], vh0[1], vh1[1], bvh);
            ldmx4(vh0[2], vh1[2], vh0[3], vh1[3], bvh + 2*1152);
            ldmx4(vh0[4], vh1[4], vh0[5], vh1[5], bvh + 4*1152);
            ldmx4(vl0[0], vl1[0], vl0[1], vl1[1], bvl);
            ldmx4(vl0[2], vl1[2], vl0[3], vl1[3], bvl + 2*1152);
            ldmx4(vl0[4], vl1[4], vl0[5], vl1[5], bvl + 4*1152);
            unsigned Ahi[4] = {Ph0[2*ksj], Ph1[2*ksj], Ph0[2*ksj+1], Ph1[2*ksj+1]};
            unsigned Alo[4] = {Pl0[2*ksj], Pl1[2*ksj], Pl0[2*ksj+1], Pl1[2*ksj+1]};
            #pragma unroll
            for (int nt2 = 0; nt2 < 6; nt2++) mma16816(o[nt2], Ahi, vh0[nt2], vh1[nt2]);
            #pragma unroll
            for (int nt2 = 0; nt2 < 6; nt2++) mma16816(o[nt2], Ahi, vl0[nt2], vl1[nt2]);
            #pragma unroll
            for (int nt2 = 0; nt2 < 6; nt2++) mma16816(o[nt2], Alo, vh0[nt2], vh1[nt2]);
        }
        __syncthreads();
    }

    #pragma unroll
    for (int off = 1; off <= 2; off <<= 1) {
        lp[0] += __shfl_xor_sync(0xffffffffu, lp[0], off);
        lp[1] += __shfl_xor_sync(0xffffffffu, lp[1], off);
    }
    float inv0 = 1.f / lp[0], inv1 = 1.f / lp[1];
    size_t base0 = ((size_t)(b*NTOK + m0 + g    ))*DIMC + h*DEPTH;
    size_t base1 = ((size_t)(b*NTOK + m0 + g + 8))*DIMC + h*DEPTH;
    #pragma unroll
    for (int nt2 = 0; nt2 < 6; nt2++) {
        unsigned hi0, lo0, hi1, lo1;
        split2(o[nt2][0]*inv0, o[nt2][1]*inv0, hi0, lo0);
        split2(o[nt2][2]*inv1, o[nt2][3]*inv1, hi1, lo1);
        int co = nt2*8 + 2*tig;
        *(unsigned*)(g_ah + base0 + co) = hi0;
        *(unsigned*)(g_al + base0 + co) = lo0;
        *(unsigned*)(g_ah + base1 + co) = hi1;
        *(unsigned*)(g_al + base1 + co) = lo1;
    }
}

// ---------------------------------------------------------------------------
// 4) Output projection + bias; smem-transposed coalesced [B,C,N] writes.
// ---------------------------------------------------------------------------
__global__ void __launch_bounds__(256) out_mma(const float* __restrict__ bias,
                                               float* __restrict__ out) {
    extern __shared__ char dsm[];
    int m0 = blockIdx.y * 128, d0 = blockIdx.x * 64;
    int tid = threadIdx.x, w = tid >> 5, lane = tid & 31;
    int g = lane >> 2, tig = lane & 3;
    int mw = w >> 1, nw = w & 1;

    float acc[2][4][4] = {};
    gemm_mainloop(dsm,
        (const unsigned*)g_ah + (size_t)m0*192, (const unsigned*)g_al + (size_t)m0*192,
        (const unsigned*)g_woh + (size_t)d0*192, (const unsigned*)g_wol + (size_t)d0*192,
        tid, mw, nw, g, tig, acc);

    int bb = m0 / NTOK, n0 = m0 - bb*NTOK;
    __syncthreads();
    float* fb = (float*)dsm;                 // [128][65]
    #pragma unroll
    for (int mi = 0; mi < 2; mi++)
        #pragma unroll
        for (int rr = 0; rr < 2; rr++) {
            int ml = mw*32 + mi*16 + g + rr*8;
            #pragma unroll
            for (int ni = 0; ni < 4; ni++)
                #pragma unroll
                for (int jj = 0; jj < 2; jj++) {
                    int dl = nw*32 + ni*8 + 2*tig + jj;
                    fb[ml*65 + dl] = acc[mi][ni][rr*2 + jj] + bias[d0 + dl];
                }
        }
    __syncthreads();
    #pragma unroll
    for (int i = tid; i < 64*128; i += 256) {
        int dl = i >> 7, n = i & 127;
        out[((size_t)bb*DIMC + d0 + dl)*NTOK + n0 + n] = fb[n*65 + dl];
    }
}

// ---------------------------------------------------------------------------
extern "C" void kernel_launch(void* const* d_in, const int* in_sizes, int n_in,
                              void* d_out, int out_size) {
    const float* feat  = (const float*)d_in[0];
    const float* gamma = (const float*)d_in[1];
    const float* beta  = (const float*)d_in[2];
    const float* tau   = (const float*)d_in[3];
    const float* w_qkv = (const float*)d_in[4];
    const float* w_out = (const float*)d_in[5];
    const float* b_out = (const float*)d_in[6];
    float* out = (float*)d_out;

    static int smem_set = 0;
    if (!smem_set) {
        cudaFuncSetAttribute(attn_mma, cudaFuncAttributeMaxDynamicSharedMemorySize, 2*ST_SZ);
        cudaFuncSetAttribute(qkv_mma, cudaFuncAttributeMaxDynamicSharedMemorySize, G_SMEM);
        cudaFuncSetAttribute(out_mma, cudaFuncAttributeMaxDynamicSharedMemorySize, G_SMEM);
        smem_set = 1;
    }

    split_w<<<(QKVD*DIMC + 255)/256, 256>>>(w_qkv, w_out);
    ln_kernel<<<dim3(NTOK/64, BATCH), 256>>>(feat, gamma, beta);
    qkv_mma<<<dim3(QKVD/64, BATCH*NTOK/128), 256, G_SMEM>>>();
    attn_mma<<<dim3(NTOK/128, NHEAD, BATCH), 256, 2*ST_SZ>>>(tau);
    out_mma<<<dim3(DIMC/64, BATCH*NTOK/128), 256, G_SMEM>>>(b_out, out);
}

// round 13
// speedup vs baseline: 1.4417x; 1.4417x over previous
#include <cuda_runtime.h>
#include <cuda_bf16.h>
#include <math.h>

#define BATCH 4
#define DIMC  384
#define NTOK  2304      // 48*48
#define NHEAD 8
#define DEPTH 48
#define QKVD  1152
#define LN_EPS 1e-5f
#define BH    (BATCH*NHEAD)
#define SM_SHIFT 40.0f

// ---------------- scratch (no allocations allowed) -------------------------
__device__ __nv_bfloat16 g_xh [BATCH*NTOK*DIMC], g_xl [BATCH*NTOK*DIMC];
__device__ __nv_bfloat16 g_ah [BATCH*NTOK*DIMC], g_al [BATCH*NTOK*DIMC];
__device__ __nv_bfloat16 g_wqh[QKVD*DIMC],       g_wql[QKVD*DIMC];
__device__ __nv_bfloat16 g_woh[DIMC*DIMC],       g_wol[DIMC*DIMC];
__device__ __nv_bfloat16 g_qhi[BH*NTOK*DEPTH], g_qlo[BH*NTOK*DEPTH];
__device__ __nv_bfloat16 g_khi[BH*NTOK*DEPTH], g_klo[BH*NTOK*DEPTH];
__device__ __nv_bfloat16 g_vthi[BH*DEPTH*NTOK], g_vtlo[BH*DEPTH*NTOK];

__device__ __forceinline__ void mma16816(float* d, const unsigned* a, unsigned b0, unsigned b1) {
    asm volatile(
        "mma.sync.aligned.m16n8k16.row.col.f32.bf16.bf16.f32 "
        "{%0,%1,%2,%3},{%4,%5,%6,%7},{%8,%9},{%0,%1,%2,%3};"
        : "+f"(d[0]), "+f"(d[1]), "+f"(d[2]), "+f"(d[3])
        : "r"(a[0]), "r"(a[1]), "r"(a[2]), "r"(a[3]), "r"(b0), "r"(b1));
}

__device__ __forceinline__ float ex2(float x) {
    float y;
    asm("ex2.approx.ftz.f32 %0, %1;" : "=f"(y) : "f"(x));
    return y;
}

// packed split: (p0,p1) -> hi bf16x2 (p0 lower), lo bf16x2 residuals
__device__ __forceinline__ void split2(float p0, float p1, unsigned& hi, unsigned& lo) {
    unsigned hbits;
    asm("cvt.rn.bf16x2.f32 %0, %1, %2;" : "=r"(hbits) : "f"(p1), "f"(p0));
    float h0 = __uint_as_float(hbits << 16);
    float h1 = __uint_as_float(hbits & 0xFFFF0000u);
    unsigned lbits;
    asm("cvt.rn.bf16x2.f32 %0, %1, %2;" : "=r"(lbits) : "f"(p1 - h1), "f"(p0 - h0));
    hi = hbits; lo = lbits;
}

__device__ __forceinline__ void cpasync16(unsigned dst, const void* src) {
    asm volatile("cp.async.cg.shared.global [%0], [%1], 16;" :: "r"(dst), "l"(src));
}
__device__ __forceinline__ unsigned smem_u32(const void* p) {
    unsigned a;
    asm("{ .reg .u64 t; cvta.to.shared.u64 t, %1; cvt.u32.u64 %0, t; }" : "=r"(a) : "l"(p));
    return a;
}

// attn smem stage layout (bytes): 128-key tiles
// K: 128 rows x 112B ; V^T: 48 rows x 272B (128 key-cols + pad)
#define ST_KH 0
#define ST_KL 14336
#define ST_VH 28672
#define ST_VL 41728
#define ST_SZ 54784

// gemm smem stage layout (32-bit words)
#define GA_H 0
#define GA_L 2560
#define GB_H 5120
#define GB_L 6400
#define G_STW 7680
#define G_STB (G_STW*4)
#define G_SMEM (2*G_STB)

// ---------------------------------------------------------------------------
__global__ void split_w(const float* __restrict__ wq, const float* __restrict__ wo) {
    int i = blockIdx.x*256 + threadIdx.x;
    if (i < QKVD*DIMC) {
        float x = wq[i];
        __nv_bfloat16 hi = __float2bfloat16_rn(x);
        g_wqh[i] = hi; g_wql[i] = __float2bfloat16_rn(x - __bfloat162float(hi));
    }
    if (i < DIMC*DIMC) {
        float x = wo[i];
        __nv_bfloat16 hi = __float2bfloat16_rn(x);
        g_woh[i] = hi; g_wol[i] = __float2bfloat16_rn(x - __bfloat162float(hi));
    }
}

// ---------------------------------------------------------------------------
// 1) LayerNorm, coalesced; register accumulation; smem-transposed writes.
// ---------------------------------------------------------------------------
__global__ void __launch_bounds__(256) ln_kernel(const float* __restrict__ feat,
                          const float* __restrict__ gamma,
                          const float* __restrict__ beta) {
    __shared__ float ps[4][64], ps2[4][64];
    __shared__ float s_mean[64], s_rstd[64];
    __shared__ __nv_bfloat16 tbh[64][66], tbl[64][66];

    int n0 = blockIdx.x * 64, b = blockIdx.y;
    int t = threadIdx.x;
    int nj = t & 63, ci4 = t >> 6;
    const float* fb = feat + (size_t)b*DIMC*NTOK + n0;

    float s = 0.f, s2 = 0.f;
    for (int c = ci4; c < DIMC; c += 4) {
        float v = fb[(size_t)c*NTOK + nj];
        s += v; s2 += v*v;
    }
    ps[ci4][nj] = s; ps2[ci4][nj] = s2;
    __syncthreads();
    if (t < 64) {
        float ts  = ps[0][t] + ps[1][t] + ps[2][t] + ps[3][t];
        float ts2 = ps2[0][t] + ps2[1][t] + ps2[2][t] + ps2[3][t];
        float mu  = ts * (1.f/DIMC);
        float var = ts2 * (1.f/DIMC) - mu*mu;
        s_mean[t] = mu;
        s_rstd[t] = rsqrtf(var + LN_EPS);
    }
    __syncthreads();

    float mu = s_mean[nj], rs = s_rstd[nj];

    for (int c0 = 0; c0 < DIMC; c0 += 64) {
        #pragma unroll
        for (int cc = 0; cc < 16; cc++) {
            int cl = cc*4 + ci4;
            int c = c0 + cl;
            float v = fb[(size_t)c*NTOK + nj];
            float x = (v - mu) * rs * gamma[c] + beta[c];
            __nv_bfloat16 hi = __float2bfloat16_rn(x);
            tbh[nj][cl] = hi;
            tbl[nj][cl] = __float2bfloat16_rn(x - __bfloat162float(hi));
        }
        __syncthreads();
        #pragma unroll
        for (int i = t; i < 64*64; i += 256) {
            int nl = i >> 6, cl = i & 63;
            size_t dst = ((size_t)(b*NTOK + n0 + nl))*DIMC + c0 + cl;
            g_xh[dst] = tbh[nl][cl];
            g_xl[dst] = tbl[nl][cl];
        }
        __syncthreads();
    }
}

// ---------------------------------------------------------------------------
// Tensor-core GEMM mainloop, cp.async double-buffered; term-major MMA order.
// ---------------------------------------------------------------------------
__device__ __forceinline__ void gemm_mainloop(
        char* dsm,
        const unsigned* Agh, const unsigned* Agl,
        const unsigned* Bgh, const unsigned* Bgl,
        int tid, int mw, int nw, int g, int tig,
        float acc[2][4][4]) {
    unsigned sbase = smem_u32(dsm);
    unsigned* smw = (unsigned*)dsm;

    auto loadc = [&](int kcw, int st) {
        unsigned base = sbase + st*G_STB;
        #pragma unroll 2
        for (int i = tid; i < 512; i += 256) {
            int r = i >> 2, c4 = (i & 3) * 4;
            cpasync16(base + (GA_H + r*20 + c4)*4, Agh + r*192 + kcw + c4);
            cpasync16(base + (GA_L + r*20 + c4)*4, Agl + r*192 + kcw + c4);
        }
        for (int i = tid; i < 256; i += 256) {
            int r = i >> 2, c4 = (i & 3) * 4;
            cpasync16(base + (GB_H + r*20 + c4)*4, Bgh + r*192 + kcw + c4);
            cpasync16(base + (GB_L + r*20 + c4)*4, Bgl + r*192 + kcw + c4);
        }
        asm volatile("cp.async.commit_group;");
    };

    loadc(0, 0);
    for (int t = 0; t < 12; t++) {
        int st = t & 1;
        asm volatile("cp.async.wait_group 0;" ::: "memory");
        __syncthreads();
        if (t + 1 < 12) loadc((t+1)*16, st ^ 1);

        const unsigned* Ah = smw + st*G_STW + GA_H;
        const unsigned* Al = smw + st*G_STW + GA_L;
        const unsigned* Bh = smw + st*G_STW + GB_H;
        const unsigned* Bl = smw + st*G_STW + GB_L;

        #pragma unroll
        for (int ks = 0; ks < 2; ks++) {
            unsigned ah[2][4], al[2][4], bh[4][2], bl[4][2];
            #pragma unroll
            for (int mi = 0; mi < 2; mi++) {
                int r = mw*32 + mi*16 + g;
                ah[mi][0] = Ah[r*20     + ks*8 + tig];
                ah[mi][1] = Ah[(r+8)*20 + ks*8 + tig];
                ah[mi][2] = Ah[r*20     + ks*8 + tig + 4];
                ah[mi][3] = Ah[(r+8)*20 + ks*8 + tig + 4];
                al[mi][0] = Al[r*20     + ks*8 + tig];
                al[mi][1] = Al[(r+8)*20 + ks*8 + tig];
                al[mi][2] = Al[r*20     + ks*8 + tig + 4];
                al[mi][3] = Al[(r+8)*20 + ks*8 + tig + 4];
            }
            #pragma unroll
            for (int ni = 0; ni < 4; ni++) {
                int n = nw*32 + ni*8 + g;
                bh[ni][0] = Bh[n*20 + ks*8 + tig];
                bh[ni][1] = Bh[n*20 + ks*8 + tig + 4];
                bl[ni][0] = Bl[n*20 + ks*8 + tig];
                bl[ni][1] = Bl[n*20 + ks*8 + tig + 4];
            }
            #pragma unroll
            for (int mi = 0; mi < 2; mi++)
                #pragma unroll
                for (int ni = 0; ni < 4; ni++)
                    mma16816(acc[mi][ni], ah[mi], bh[ni][0], bh[ni][1]);
            #pragma unroll
            for (int mi = 0; mi < 2; mi++)
                #pragma unroll
                for (int ni = 0; ni < 4; ni++)
                    mma16816(acc[mi][ni], ah[mi], bl[ni][0], bl[ni][1]);
            #pragma unroll
            for (int mi = 0; mi < 2; mi++)
                #pragma unroll
                for (int ni = 0; ni < 4; ni++)
                    mma16816(acc[mi][ni], al[mi], bh[ni][0], bh[ni][1]);
        }
    }
}

// ---------------------------------------------------------------------------
// 2) QKV projection GEMM; q/k direct scatter, V transposed through smem.
// ---------------------------------------------------------------------------
__global__ void __launch_bounds__(256) qkv_mma() {
    extern __shared__ char dsm[];
    int m0 = blockIdx.y * 128, d0 = blockIdx.x * 64;
    int tid = threadIdx.x, w = tid >> 5, lane = tid & 31;
    int g = lane >> 2, tig = lane & 3;
    int mw = w >> 1, nw = w & 1;

    float acc[2][4][4] = {};
    gemm_mainloop(dsm,
        (const unsigned*)g_xh + (size_t)m0*192, (const unsigned*)g_xl + (size_t)m0*192,
        (const unsigned*)g_wqh + (size_t)d0*192, (const unsigned*)g_wql + (size_t)d0*192,
        tid, mw, nw, g, tig, acc);

    int which = d0 / DIMC;
    int r0 = d0 - which*DIMC;
    int bb = m0 / NTOK, n0 = m0 - bb*NTOK;

    if (which < 2) {
        #pragma unroll
        for (int mi = 0; mi < 2; mi++) {
            #pragma unroll
            for (int rr = 0; rr < 2; rr++) {
                int n = n0 + mw*32 + mi*16 + g + rr*8;
                #pragma unroll
                for (int ni = 0; ni < 4; ni++) {
                    int d = r0 + nw*32 + ni*8 + 2*tig;
                    int h = d / DEPTH, dd = d - h*DEPTH;
                    int bhI = bb*NHEAD + h;
                    unsigned hi, lo;
                    split2(acc[mi][ni][rr*2], acc[mi][ni][rr*2+1], hi, lo);
                    size_t idx = ((size_t)bhI*NTOK + n)*DEPTH + dd;
                    if (which == 0) { *(unsigned*)(g_qhi+idx) = hi; *(unsigned*)(g_qlo+idx) = lo; }
                    else            { *(unsigned*)(g_khi+idx) = hi; *(unsigned*)(g_klo+idx) = lo; }
                }
            }
        }
    } else {
        __syncthreads();
        __nv_bfloat16* th = (__nv_bfloat16*)dsm;           // [64][130]
        __nv_bfloat16* tl = th + 64*130;
        #pragma unroll
        for (int mi = 0; mi < 2; mi++)
            #pragma unroll
            for (int rr = 0; rr < 2; rr++) {
                int ml = mw*32 + mi*16 + g + rr*8;
                #pragma unroll
                for (int ni = 0; ni < 4; ni++)
                    #pragma unroll
                    for (int jj = 0; jj < 2; jj++) {
                        int dl = nw*32 + ni*8 + 2*tig + jj;
                        float x = acc[mi][ni][rr*2 + jj];
                        __nv_bfloat16 hi = __float2bfloat16_rn(x);
                        th[dl*130 + ml] = hi;
                        tl[dl*130 + ml] = __float2bfloat16_rn(x - __bfloat162float(hi));
                    }
            }
        __syncthreads();
        #pragma unroll
        for (int i = tid; i < 64*128; i += 256) {
            int dl = i >> 7, n = i & 127;
            int rg = r0 + dl;
            int h = rg / DEPTH, dd = rg - h*DEPTH;
            size_t idx = ((size_t)(bb*NHEAD + h)*DEPTH + dd)*NTOK + n0 + n;
            g_vthi[idx] = th[dl*130 + n];
            g_vtlo[idx] = tl[dl*130 + n];
        }
    }
}

// ---------------------------------------------------------------------------
// 3) Tensor-core flash attention; 256 threads / 128 queries per block;
//    128-key staged tiles processed as two 64-key passes (half the barriers);
//    batched ex2.approx softmax; term-major scalar-LDS fragment loads (R10).
// ---------------------------------------------------------------------------
__global__ void __launch_bounds__(256, 2) attn_mma(const float* __restrict__ tau) {
    extern __shared__ char dsm[];

    int qc = blockIdx.x, h = blockIdx.y, b = blockIdx.z;
    int bh = b*NHEAD + h;
    int tid = threadIdx.x, w = tid >> 5, lane = tid & 31;
    int g = lane >> 2, tig = lane & 3;
    float scale2 = expf(tau[h]) * 1.44269504088896f;
    int m0 = qc*128 + w*16;

    const char* Kh_src = (const char*)(g_khi + (size_t)bh*NTOK*DEPTH);
    const char* Kl_src = (const char*)(g_klo + (size_t)bh*NTOK*DEPTH);
    const char* Vh_src = (const char*)(g_vthi + (size_t)bh*DEPTH*NTOK);
    const char* Vl_src = (const char*)(g_vtlo + (size_t)bh*DEPTH*NTOK);
    unsigned sbase = smem_u32(dsm);

    const __nv_bfloat16* qh = g_qhi + (size_t)bh*NTOK*DEPTH;
    const __nv_bfloat16* ql = g_qlo + (size_t)bh*NTOK*DEPTH;
    unsigned aqh[3][4], aql[3][4];
    #pragma unroll
    for (int ks = 0; ks < 3; ks++) {
        int c0 = ks*16 + 2*tig;
        aqh[ks][0] = *(const unsigned*)(qh + (size_t)(m0+g  )*DEPTH + c0);
        aqh[ks][1] = *(const unsigned*)(qh + (size_t)(m0+g+8)*DEPTH + c0);
        aqh[ks][2] = *(const unsigned*)(qh + (size_t)(m0+g  )*DEPTH + c0 + 8);
        aqh[ks][3] = *(const unsigned*)(qh + (size_t)(m0+g+8)*DEPTH + c0 + 8);
        aql[ks][0] = *(const unsigned*)(ql + (size_t)(m0+g  )*DEPTH + c0);
        aql[ks][1] = *(const unsigned*)(ql + (size_t)(m0+g+8)*DEPTH + c0);
        aql[ks][2] = *(const unsigned*)(ql + (size_t)(m0+g  )*DEPTH + c0 + 8);
        aql[ks][3] = *(const unsigned*)(ql + (size_t)(m0+g+8)*DEPTH + c0 + 8);
    }

    float o[6][4] = {};
    float lp[2] = {0.f, 0.f};

    // stage 128 keys: K rows 112B-stride, V rows 272B-stride (128 key cols)
    auto load_tile = [&](int j0, int st) {
        unsigned base = sbase + st*ST_SZ;
        for (int i = tid; i < 768; i += 256) {
            int row = i / 6, c = i % 6;
            size_t src = (size_t)(j0 + row)*96 + c*16;
            cpasync16(base + ST_KH + row*112 + c*16, Kh_src + src);
            cpasync16(base + ST_KL + row*112 + c*16, Kl_src + src);
        }
        for (int i = tid; i < 768; i += 256) {
            int row = i / 16, c = i % 16;
            size_t src = ((size_t)row*NTOK + j0)*2 + c*16;
            cpasync16(base + ST_VH + row*272 + c*16, Vh_src + src);
            cpasync16(base + ST_VL + row*272 + c*16, Vl_src + src);
        }
        asm volatile("cp.async.commit_group;");
    };

    load_tile(0, 0);

    for (int t = 0; t < NTOK/128; t++) {
        int st = t & 1;
        asm volatile("cp.async.wait_group 0;" ::: "memory");
        __syncthreads();
        if (t + 1 < NTOK/128) load_tile((t+1)*128, st ^ 1);

        #pragma unroll
        for (int pass = 0; pass < 2; pass++) {
            const __nv_bfloat16* Kh = (const __nv_bfloat16*)(dsm + st*ST_SZ + ST_KH + pass*64*112);
            const __nv_bfloat16* Kl = (const __nv_bfloat16*)(dsm + st*ST_SZ + ST_KL + pass*64*112);
            const __nv_bfloat16* Vh = (const __nv_bfloat16*)(dsm + st*ST_SZ + ST_VH + pass*128);
            const __nv_bfloat16* Vl = (const __nv_bfloat16*)(dsm + st*ST_SZ + ST_VL + pass*128);

            // ---- S = Q K^T: groups of 4 accumulators, term-major inside group
            float s[8][4];
            #pragma unroll
            for (int nt = 0; nt < 8; nt++) { s[nt][0]=0.f; s[nt][1]=0.f; s[nt][2]=0.f; s[nt][3]=0.f; }
            #pragma unroll
            for (int ks = 0; ks < 3; ks++) {
                #pragma unroll
                for (int h4 = 0; h4 < 8; h4 += 4) {
                    unsigned kb0[4], kb1[4], kl0[4], kl1[4];
                    #pragma unroll
                    for (int j = 0; j < 4; j++) {
                        const __nv_bfloat16* krh = Kh + (h4*8 + j*8 + g)*56 + ks*16 + 2*tig;
                        const __nv_bfloat16* krl = Kl + (h4*8 + j*8 + g)*56 + ks*16 + 2*tig;
                        kb0[j] = *(const unsigned*)(krh);
                        kb1[j] = *(const unsigned*)(krh + 8);
                        kl0[j] = *(const unsigned*)(krl);
                        kl1[j] = *(const unsigned*)(krl + 8);
                    }
                    #pragma unroll
                    for (int j = 0; j < 4; j++) mma16816(s[h4+j], aqh[ks], kb0[j], kb1[j]);
                    #pragma unroll
                    for (int j = 0; j < 4; j++) mma16816(s[h4+j], aqh[ks], kl0[j], kl1[j]);
                    #pragma unroll
                    for (int j = 0; j < 4; j++) mma16816(s[h4+j], aql[ks], kb0[j], kb1[j]);
                }
            }

            // ---- P = ex2(s*scale2 - SHIFT): 32 independent MUFUs, then splits
            unsigned Ph0[8], Ph1[8], Pl0[8], Pl1[8];
            #pragma unroll
            for (int nt = 0; nt < 8; nt++) {
                float p0 = ex2(fmaf(s[nt][0], scale2, -SM_SHIFT));
                float p1 = ex2(fmaf(s[nt][1], scale2, -SM_SHIFT));
                float p2 = ex2(fmaf(s[nt][2], scale2, -SM_SHIFT));
                float p3 = ex2(fmaf(s[nt][3], scale2, -SM_SHIFT));
                lp[0] += p0 + p1; lp[1] += p2 + p3;
                split2(p0, p1, Ph0[nt], Pl0[nt]);
                split2(p2, p3, Ph1[nt], Pl1[nt]);
            }

            // ---- O += P V: ksj-outer, rotate over 6 accumulators per term
            #pragma unroll
            for (int ksj = 0; ksj < 4; ksj++) {
                unsigned vh0[6], vh1[6], vl0[6], vl1[6];
                #pragma unroll
                for (int nt2 = 0; nt2 < 6; nt2++) {
                    const __nv_bfloat16* vrh = Vh + (nt2*8 + g)*136 + ksj*16 + 2*tig;
                    const __nv_bfloat16* vrl = Vl + (nt2*8 + g)*136 + ksj*16 + 2*tig;
                    vh0[nt2] = *(const unsigned*)(vrh);
                    vh1[nt2] = *(const unsigned*)(vrh + 8);
                    vl0[nt2] = *(const unsigned*)(vrl);
                    vl1[nt2] = *(const unsigned*)(vrl + 8);
                }
                unsigned Ahi[4] = {Ph0[2*ksj], Ph1[2*ksj], Ph0[2*ksj+1], Ph1[2*ksj+1]};
                unsigned Alo[4] = {Pl0[2*ksj], Pl1[2*ksj], Pl0[2*ksj+1], Pl1[2*ksj+1]};
                #pragma unroll
                for (int nt2 = 0; nt2 < 6; nt2++) mma16816(o[nt2], Ahi, vh0[nt2], vh1[nt2]);
                #pragma unroll
                for (int nt2 = 0; nt2 < 6; nt2++) mma16816(o[nt2], Ahi, vl0[nt2], vl1[nt2]);
                #pragma unroll
                for (int nt2 = 0; nt2 < 6; nt2++) mma16816(o[nt2], Alo, vh0[nt2], vh1[nt2]);
            }
        }
        __syncthreads();
    }

    #pragma unroll
    for (int off = 1; off <= 2; off <<= 1) {
        lp[0] += __shfl_xor_sync(0xffffffffu, lp[0], off);
        lp[1] += __shfl_xor_sync(0xffffffffu, lp[1], off);
    }
    float inv0 = 1.f / lp[0], inv1 = 1.f / lp[1];
    size_t base0 = ((size_t)(b*NTOK + m0 + g    ))*DIMC + h*DEPTH;
    size_t base1 = ((size_t)(b*NTOK + m0 + g + 8))*DIMC + h*DEPTH;
    #pragma unroll
    for (int nt2 = 0; nt2 < 6; nt2++) {
        unsigned hi0, lo0, hi1, lo1;
        split2(o[nt2][0]*inv0, o[nt2][1]*inv0, hi0, lo0);
        split2(o[nt2][2]*inv1, o[nt2][3]*inv1, hi1, lo1);
        int co = nt2*8 + 2*tig;
        *(unsigned*)(g_ah + base0 + co) = hi0;
        *(unsigned*)(g_al + base0 + co) = lo0;
        *(unsigned*)(g_ah + base1 + co) = hi1;
        *(unsigned*)(g_al + base1 + co) = lo1;
    }
}

// ---------------------------------------------------------------------------
// 4) Output projection + bias; smem-transposed coalesced [B,C,N] writes.
// ---------------------------------------------------------------------------
__global__ void __launch_bounds__(256) out_mma(const float* __restrict__ bias,
                                               float* __restrict__ out) {
    extern __shared__ char dsm[];
    int m0 = blockIdx.y * 128, d0 = blockIdx.x * 64;
    int tid = threadIdx.x, w = tid >> 5, lane = tid & 31;
    int g = lane >> 2, tig = lane & 3;
    int mw = w >> 1, nw = w & 1;

    float acc[2][4][4] = {};
    gemm_mainloop(dsm,
        (const unsigned*)g_ah + (size_t)m0*192, (const unsigned*)g_al + (size_t)m0*192,
        (const unsigned*)g_woh + (size_t)d0*192, (const unsigned*)g_wol + (size_t)d0*192,
        tid, mw, nw, g, tig, acc);

    int bb = m0 / NTOK, n0 = m0 - bb*NTOK;
    __syncthreads();
    float* fb = (float*)dsm;                 // [128][65]
    #pragma unroll
    for (int mi = 0; mi < 2; mi++)
        #pragma unroll
        for (int rr = 0; rr < 2; rr++) {
            int ml = mw*32 + mi*16 + g + rr*8;
            #pragma unroll
            for (int ni = 0; ni < 4; ni++)
                #pragma unroll
                for (int jj = 0; jj < 2; jj++) {
                    int dl = nw*32 + ni*8 + 2*tig + jj;
                    fb[ml*65 + dl] = acc[mi][ni][rr*2 + jj] + bias[d0 + dl];
                }
        }
    __syncthreads();
    #pragma unroll
    for (int i = tid; i < 64*128; i += 256) {
        int dl = i >> 7, n = i & 127;
        out[((size_t)bb*DIMC + d0 + dl)*NTOK + n0 + n] = fb[n*65 + dl];
    }
}

// ---------------------------------------------------------------------------
extern "C" void kernel_launch(void* const* d_in, const int* in_sizes, int n_in,
                              void* d_out, int out_size) {
    const float* feat  = (const float*)d_in[0];
    const float* gamma = (const float*)d_in[1];
    const float* beta  = (const float*)d_in[2];
    const float* tau   = (const float*)d_in[3];
    const float* w_qkv = (const float*)d_in[4];
    const float* w_out = (const float*)d_in[5];
    const float* b_out = (const float*)d_in[6];
    float* out = (float*)d_out;

    static int smem_set = 0;
    if (!smem_set) {
        cudaFuncSetAttribute(attn_mma, cudaFuncAttributeMaxDynamicSharedMemorySize, 2*ST_SZ);
        cudaFuncSetAttribute(qkv_mma, cudaFuncAttributeMaxDynamicSharedMemorySize, G_SMEM);
        cudaFuncSetAttribute(out_mma, cudaFuncAttributeMaxDynamicSharedMemorySize, G_SMEM);
        smem_set = 1;
    }

    split_w<<<(QKVD*DIMC + 255)/256, 256>>>(w_qkv, w_out);
    ln_kernel<<<dim3(NTOK/64, BATCH), 256>>>(feat, gamma, beta);
    qkv_mma<<<dim3(QKVD/64, BATCH*NTOK/128), 256, G_SMEM>>>();
    attn_mma<<<dim3(NTOK/128, NHEAD, BATCH), 256, 2*ST_SZ>>>(tau);
    out_mma<<<dim3(DIMC/64, BATCH*NTOK/128), 256, G_SMEM>>>(b_out, out);
}

// round 14
// speedup vs baseline: 1.5124x; 1.0491x over previous
#include <cuda_runtime.h>
#include <cuda_bf16.h>
#include <math.h>

#define BATCH 4
#define DIMC  384
#define NTOK  2304      // 48*48
#define NHEAD 8
#define DEPTH 48
#define QKVD  1152
#define LN_EPS 1e-5f
#define BH    (BATCH*NHEAD)
#define SM_SHIFT 40.0f

// ---------------- scratch (no allocations allowed) -------------------------
__device__ __nv_bfloat16 g_xh [BATCH*NTOK*DIMC], g_xl [BATCH*NTOK*DIMC];
__device__ __nv_bfloat16 g_ah [BATCH*NTOK*DIMC], g_al [BATCH*NTOK*DIMC];
__device__ __nv_bfloat16 g_wqh[QKVD*DIMC],       g_wql[QKVD*DIMC];
__device__ __nv_bfloat16 g_woh[DIMC*DIMC],       g_wol[DIMC*DIMC];
__device__ __nv_bfloat16 g_qhi[BH*NTOK*DEPTH], g_qlo[BH*NTOK*DEPTH];
__device__ __nv_bfloat16 g_khi[BH*NTOK*DEPTH], g_klo[BH*NTOK*DEPTH];
__device__ __nv_bfloat16 g_vthi[BH*DEPTH*NTOK], g_vtlo[BH*DEPTH*NTOK];

__device__ __forceinline__ void mma16816(float* d, const unsigned* a, unsigned b0, unsigned b1) {
    asm volatile(
        "mma.sync.aligned.m16n8k16.row.col.f32.bf16.bf16.f32 "
        "{%0,%1,%2,%3},{%4,%5,%6,%7},{%8,%9},{%0,%1,%2,%3};"
        : "+f"(d[0]), "+f"(d[1]), "+f"(d[2]), "+f"(d[3])
        : "r"(a[0]), "r"(a[1]), "r"(a[2]), "r"(a[3]), "r"(b0), "r"(b1));
}

__device__ __forceinline__ float ex2(float x) {
    float y;
    asm("ex2.approx.ftz.f32 %0, %1;" : "=f"(y) : "f"(x));
    return y;
}

// packed split: (p0,p1) -> hi bf16x2 (p0 lower), lo bf16x2 residuals
__device__ __forceinline__ void split2(float p0, float p1, unsigned& hi, unsigned& lo) {
    unsigned hbits;
    asm("cvt.rn.bf16x2.f32 %0, %1, %2;" : "=r"(hbits) : "f"(p1), "f"(p0));
    float h0 = __uint_as_float(hbits << 16);
    float h1 = __uint_as_float(hbits & 0xFFFF0000u);
    unsigned lbits;
    asm("cvt.rn.bf16x2.f32 %0, %1, %2;" : "=r"(lbits) : "f"(p1 - h1), "f"(p0 - h0));
    hi = hbits; lo = lbits;
}

__device__ __forceinline__ void cpasync16(unsigned dst, const void* src) {
    asm volatile("cp.async.cg.shared.global [%0], [%1], 16;" :: "r"(dst), "l"(src));
}
__device__ __forceinline__ unsigned smem_u32(const void* p) {
    unsigned a;
    asm("{ .reg .u64 t; cvta.to.shared.u64 t, %1; cvt.u32.u64 %0, t; }" : "=r"(a) : "l"(p));
    return a;
}

// attn smem stage layout (bytes) — R10 proven config
#define ST_KH 0
#define ST_KL 7168
#define ST_VH 14336
#define ST_VL 21248
#define ST_SZ 28160

// gemm smem stage layout (32-bit words): 32-word k-chunks, 36-word row stride
#define GA_H 0
#define GA_L 4608
#define GB_H 9216
#define GB_L 11520
#define G_STW 13824
#define G_STB (G_STW*4)
#define G_SMEM (2*G_STB)

// ---------------------------------------------------------------------------
__global__ void split_w(const float* __restrict__ wq, const float* __restrict__ wo) {
    int i = blockIdx.x*256 + threadIdx.x;
    if (i < QKVD*DIMC) {
        float x = wq[i];
        __nv_bfloat16 hi = __float2bfloat16_rn(x);
        g_wqh[i] = hi; g_wql[i] = __float2bfloat16_rn(x - __bfloat162float(hi));
    }
    if (i < DIMC*DIMC) {
        float x = wo[i];
        __nv_bfloat16 hi = __float2bfloat16_rn(x);
        g_woh[i] = hi; g_wol[i] = __float2bfloat16_rn(x - __bfloat162float(hi));
    }
}

// ---------------------------------------------------------------------------
// 1) LayerNorm, coalesced; register accumulation; smem-transposed writes.
// ---------------------------------------------------------------------------
__global__ void __launch_bounds__(256) ln_kernel(const float* __restrict__ feat,
                          const float* __restrict__ gamma,
                          const float* __restrict__ beta) {
    __shared__ float ps[4][64], ps2[4][64];
    __shared__ float s_mean[64], s_rstd[64];
    __shared__ __nv_bfloat16 tbh[64][66], tbl[64][66];

    int n0 = blockIdx.x * 64, b = blockIdx.y;
    int t = threadIdx.x;
    int nj = t & 63, ci4 = t >> 6;
    const float* fb = feat + (size_t)b*DIMC*NTOK + n0;

    float s = 0.f, s2 = 0.f;
    for (int c = ci4; c < DIMC; c += 4) {
        float v = fb[(size_t)c*NTOK + nj];
        s += v; s2 += v*v;
    }
    ps[ci4][nj] = s; ps2[ci4][nj] = s2;
    __syncthreads();
    if (t < 64) {
        float ts  = ps[0][t] + ps[1][t] + ps[2][t] + ps[3][t];
        float ts2 = ps2[0][t] + ps2[1][t] + ps2[2][t] + ps2[3][t];
        float mu  = ts * (1.f/DIMC);
        float var = ts2 * (1.f/DIMC) - mu*mu;
        s_mean[t] = mu;
        s_rstd[t] = rsqrtf(var + LN_EPS);
    }
    __syncthreads();

    float mu = s_mean[nj], rs = s_rstd[nj];

    for (int c0 = 0; c0 < DIMC; c0 += 64) {
        #pragma unroll
        for (int cc = 0; cc < 16; cc++) {
            int cl = cc*4 + ci4;
            int c = c0 + cl;
            float v = fb[(size_t)c*NTOK + nj];
            float x = (v - mu) * rs * gamma[c] + beta[c];
            __nv_bfloat16 hi = __float2bfloat16_rn(x);
            tbh[nj][cl] = hi;
            tbl[nj][cl] = __float2bfloat16_rn(x - __bfloat162float(hi));
        }
        __syncthreads();
        #pragma unroll
        for (int i = t; i < 64*64; i += 256) {
            int nl = i >> 6, cl = i & 63;
            size_t dst = ((size_t)(b*NTOK + n0 + nl))*DIMC + c0 + cl;
            g_xh[dst] = tbh[nl][cl];
            g_xl[dst] = tbl[nl][cl];
        }
        __syncthreads();
    }
}

// ---------------------------------------------------------------------------
// Tensor-core GEMM mainloop: 6 k-chunks of 64 values, cp.async double-buffer,
// term-major MMA order. Half the barriers of the 16-word-chunk version.
// ---------------------------------------------------------------------------
__device__ __forceinline__ void gemm_mainloop(
        char* dsm,
        const unsigned* Agh, const unsigned* Agl,
        const unsigned* Bgh, const unsigned* Bgl,
        int tid, int mw, int nw, int g, int tig,
        float acc[2][4][4]) {
    unsigned sbase = smem_u32(dsm);
    unsigned* smw = (unsigned*)dsm;

    auto loadc = [&](int kcw, int st) {
        unsigned base = sbase + st*G_STB;
        #pragma unroll 4
        for (int i = tid; i < 1024; i += 256) {
            int r = i >> 3, c4 = (i & 7) * 4;
            cpasync16(base + (GA_H + r*36 + c4)*4, Agh + r*192 + kcw + c4);
            cpasync16(base + (GA_L + r*36 + c4)*4, Agl + r*192 + kcw + c4);
        }
        #pragma unroll 2
        for (int i = tid; i < 512; i += 256) {
            int r = i >> 3, c4 = (i & 7) * 4;
            cpasync16(base + (GB_H + r*36 + c4)*4, Bgh + r*192 + kcw + c4);
            cpasync16(base + (GB_L + r*36 + c4)*4, Bgl + r*192 + kcw + c4);
        }
        asm volatile("cp.async.commit_group;");
    };

    loadc(0, 0);
    for (int t = 0; t < 6; t++) {
        int st = t & 1;
        asm volatile("cp.async.wait_group 0;" ::: "memory");
        __syncthreads();
        if (t + 1 < 6) loadc((t+1)*32, st ^ 1);

        const unsigned* Ah = smw + st*G_STW + GA_H;
        const unsigned* Al = smw + st*G_STW + GA_L;
        const unsigned* Bh = smw + st*G_STW + GB_H;
        const unsigned* Bl = smw + st*G_STW + GB_L;

        #pragma unroll
        for (int ks = 0; ks < 4; ks++) {
            unsigned ah[2][4], al[2][4], bh[4][2], bl[4][2];
            #pragma unroll
            for (int mi = 0; mi < 2; mi++) {
                int r = mw*32 + mi*16 + g;
                ah[mi][0] = Ah[r*36     + ks*8 + tig];
                ah[mi][1] = Ah[(r+8)*36 + ks*8 + tig];
                ah[mi][2] = Ah[r*36     + ks*8 + tig + 4];
                ah[mi][3] = Ah[(r+8)*36 + ks*8 + tig + 4];
                al[mi][0] = Al[r*36     + ks*8 + tig];
                al[mi][1] = Al[(r+8)*36 + ks*8 + tig];
                al[mi][2] = Al[r*36     + ks*8 + tig + 4];
                al[mi][3] = Al[(r+8)*36 + ks*8 + tig + 4];
            }
            #pragma unroll
            for (int ni = 0; ni < 4; ni++) {
                int n = nw*32 + ni*8 + g;
                bh[ni][0] = Bh[n*36 + ks*8 + tig];
                bh[ni][1] = Bh[n*36 + ks*8 + tig + 4];
                bl[ni][0] = Bl[n*36 + ks*8 + tig];
                bl[ni][1] = Bl[n*36 + ks*8 + tig + 4];
            }
            #pragma unroll
            for (int mi = 0; mi < 2; mi++)
                #pragma unroll
                for (int ni = 0; ni < 4; ni++)
                    mma16816(acc[mi][ni], ah[mi], bh[ni][0], bh[ni][1]);
            #pragma unroll
            for (int mi = 0; mi < 2; mi++)
                #pragma unroll
                for (int ni = 0; ni < 4; ni++)
                    mma16816(acc[mi][ni], ah[mi], bl[ni][0], bl[ni][1]);
            #pragma unroll
            for (int mi = 0; mi < 2; mi++)
                #pragma unroll
                for (int ni = 0; ni < 4; ni++)
                    mma16816(acc[mi][ni], al[mi], bh[ni][0], bh[ni][1]);
        }
    }
}

// ---------------------------------------------------------------------------
// 2) QKV projection GEMM; q/k direct scatter, V transposed through smem.
// ---------------------------------------------------------------------------
__global__ void __launch_bounds__(256) qkv_mma() {
    extern __shared__ char dsm[];
    int m0 = blockIdx.y * 128, d0 = blockIdx.x * 64;
    int tid = threadIdx.x, w = tid >> 5, lane = tid & 31;
    int g = lane >> 2, tig = lane & 3;
    int mw = w >> 1, nw = w & 1;

    float acc[2][4][4] = {};
    gemm_mainloop(dsm,
        (const unsigned*)g_xh + (size_t)m0*192, (const unsigned*)g_xl + (size_t)m0*192,
        (const unsigned*)g_wqh + (size_t)d0*192, (const unsigned*)g_wql + (size_t)d0*192,
        tid, mw, nw, g, tig, acc);

    int which = d0 / DIMC;
    int r0 = d0 - which*DIMC;
    int bb = m0 / NTOK, n0 = m0 - bb*NTOK;

    if (which < 2) {
        #pragma unroll
        for (int mi = 0; mi < 2; mi++) {
            #pragma unroll
            for (int rr = 0; rr < 2; rr++) {
                int n = n0 + mw*32 + mi*16 + g + rr*8;
                #pragma unroll
                for (int ni = 0; ni < 4; ni++) {
                    int d = r0 + nw*32 + ni*8 + 2*tig;
                    int h = d / DEPTH, dd = d - h*DEPTH;
                    int bhI = bb*NHEAD + h;
                    unsigned hi, lo;
                    split2(acc[mi][ni][rr*2], acc[mi][ni][rr*2+1], hi, lo);
                    size_t idx = ((size_t)bhI*NTOK + n)*DEPTH + dd;
                    if (which == 0) { *(unsigned*)(g_qhi+idx) = hi; *(unsigned*)(g_qlo+idx) = lo; }
                    else            { *(unsigned*)(g_khi+idx) = hi; *(unsigned*)(g_klo+idx) = lo; }
                }
            }
        }
    } else {
        __syncthreads();
        __nv_bfloat16* th = (__nv_bfloat16*)dsm;           // [64][130]
        __nv_bfloat16* tl = th + 64*130;
        #pragma unroll
        for (int mi = 0; mi < 2; mi++)
            #pragma unroll
            for (int rr = 0; rr < 2; rr++) {
                int ml = mw*32 + mi*16 + g + rr*8;
                #pragma unroll
                for (int ni = 0; ni < 4; ni++)
                    #pragma unroll
                    for (int jj = 0; jj < 2; jj++) {
                        int dl = nw*32 + ni*8 + 2*tig + jj;
                        float x = acc[mi][ni][rr*2 + jj];
                        __nv_bfloat16 hi = __float2bfloat16_rn(x);
                        th[dl*130 + ml] = hi;
                        tl[dl*130 + ml] = __float2bfloat16_rn(x - __bfloat162float(hi));
                    }
            }
        __syncthreads();
        #pragma unroll
        for (int i = tid; i < 64*128; i += 256) {
            int dl = i >> 7, n = i & 127;
            int rg = r0 + dl;
            int h = rg / DEPTH, dd = rg - h*DEPTH;
            size_t idx = ((size_t)(bb*NHEAD + h)*DEPTH + dd)*NTOK + n0 + n;
            g_vthi[idx] = th[dl*130 + n];
            g_vtlo[idx] = tl[dl*130 + n];
        }
    }
}

// ---------------------------------------------------------------------------
// 3) Tensor-core flash attention — exact R10 winner: 256 threads / 128
//    queries per block, 64-key double-buffered tiles, batched ex2.approx
//    softmax, term-major scalar-LDS fragment loads.
// ---------------------------------------------------------------------------
__global__ void __launch_bounds__(256, 2) attn_mma(const float* __restrict__ tau) {
    extern __shared__ char dsm[];

    int qc = blockIdx.x, h = blockIdx.y, b = blockIdx.z;
    int bh = b*NHEAD + h;
    int tid = threadIdx.x, w = tid >> 5, lane = tid & 31;
    int g = lane >> 2, tig = lane & 3;
    float scale2 = expf(tau[h]) * 1.44269504088896f;
    int m0 = qc*128 + w*16;

    const char* Kh_src = (const char*)(g_khi + (size_t)bh*NTOK*DEPTH);
    const char* Kl_src = (const char*)(g_klo + (size_t)bh*NTOK*DEPTH);
    const char* Vh_src = (const char*)(g_vthi + (size_t)bh*DEPTH*NTOK);
    const char* Vl_src = (const char*)(g_vtlo + (size_t)bh*DEPTH*NTOK);
    unsigned sbase = smem_u32(dsm);

    const __nv_bfloat16* qh = g_qhi + (size_t)bh*NTOK*DEPTH;
    const __nv_bfloat16* ql = g_qlo + (size_t)bh*NTOK*DEPTH;
    unsigned aqh[3][4], aql[3][4];
    #pragma unroll
    for (int ks = 0; ks < 3; ks++) {
        int c0 = ks*16 + 2*tig;
        aqh[ks][0] = *(const unsigned*)(qh + (size_t)(m0+g  )*DEPTH + c0);
        aqh[ks][1] = *(const unsigned*)(qh + (size_t)(m0+g+8)*DEPTH + c0);
        aqh[ks][2] = *(const unsigned*)(qh + (size_t)(m0+g  )*DEPTH + c0 + 8);
        aqh[ks][3] = *(const unsigned*)(qh + (size_t)(m0+g+8)*DEPTH + c0 + 8);
        aql[ks][0] = *(const unsigned*)(ql + (size_t)(m0+g  )*DEPTH + c0);
        aql[ks][1] = *(const unsigned*)(ql + (size_t)(m0+g+8)*DEPTH + c0);
        aql[ks][2] = *(const unsigned*)(ql + (size_t)(m0+g  )*DEPTH + c0 + 8);
        aql[ks][3] = *(const unsigned*)(ql + (size_t)(m0+g+8)*DEPTH + c0 + 8);
    }

    float o[6][4] = {};
    float lp[2] = {0.f, 0.f};

    auto load_tile = [&](int j0, int st) {
        unsigned base = sbase + st*ST_SZ;
        for (int i = tid; i < 384; i += 256) {
            int row = i / 6, c = i % 6;
            size_t src = (size_t)(j0 + row)*96 + c*16;
            cpasync16(base + ST_KH + row*112 + c*16, Kh_src + src);
            cpasync16(base + ST_KL + row*112 + c*16, Kl_src + src);
        }
        for (int i = tid; i < 384; i += 256) {
            int row = i / 8, c = i % 8;
            size_t src = ((size_t)row*NTOK + j0)*2 + c*16;
            cpasync16(base + ST_VH + row*144 + c*16, Vh_src + src);
            cpasync16(base + ST_VL + row*144 + c*16, Vl_src + src);
        }
        asm volatile("cp.async.commit_group;");
    };

    load_tile(0, 0);

    for (int t = 0; t < NTOK/64; t++) {
        int st = t & 1;
        asm volatile("cp.async.wait_group 0;" ::: "memory");
        __syncthreads();
        if (t + 1 < NTOK/64) load_tile((t+1)*64, st ^ 1);

        const __nv_bfloat16* Kh = (const __nv_bfloat16*)(dsm + st*ST_SZ + ST_KH);
        const __nv_bfloat16* Kl = (const __nv_bfloat16*)(dsm + st*ST_SZ + ST_KL);
        const __nv_bfloat16* Vh = (const __nv_bfloat16*)(dsm + st*ST_SZ + ST_VH);
        const __nv_bfloat16* Vl = (const __nv_bfloat16*)(dsm + st*ST_SZ + ST_VL);

        // ---- S = Q K^T: groups of 4 accumulators, term-major inside group
        float s[8][4];
        #pragma unroll
        for (int nt = 0; nt < 8; nt++) { s[nt][0]=0.f; s[nt][1]=0.f; s[nt][2]=0.f; s[nt][3]=0.f; }
        #pragma unroll
        for (int ks = 0; ks < 3; ks++) {
            #pragma unroll
            for (int h4 = 0; h4 < 8; h4 += 4) {
                unsigned kb0[4], kb1[4], kl0[4], kl1[4];
                #pragma unroll
                for (int j = 0; j < 4; j++) {
                    const __nv_bfloat16* krh = Kh + (h4*8 + j*8 + g)*56 + ks*16 + 2*tig;
                    const __nv_bfloat16* krl = Kl + (h4*8 + j*8 + g)*56 + ks*16 + 2*tig;
                    kb0[j] = *(const unsigned*)(krh);
                    kb1[j] = *(const unsigned*)(krh + 8);
                    kl0[j] = *(const unsigned*)(krl);
                    kl1[j] = *(const unsigned*)(krl + 8);
                }
                #pragma unroll
                for (int j = 0; j < 4; j++) mma16816(s[h4+j], aqh[ks], kb0[j], kb1[j]);
                #pragma unroll
                for (int j = 0; j < 4; j++) mma16816(s[h4+j], aqh[ks], kl0[j], kl1[j]);
                #pragma unroll
                for (int j = 0; j < 4; j++) mma16816(s[h4+j], aql[ks], kb0[j], kb1[j]);
            }
        }

        // ---- P = ex2(s*scale2 - SHIFT): 32 independent MUFUs, then splits
        unsigned Ph0[8], Ph1[8], Pl0[8], Pl1[8];
        #pragma unroll
        for (int nt = 0; nt < 8; nt++) {
            float p0 = ex2(fmaf(s[nt][0], scale2, -SM_SHIFT));
            float p1 = ex2(fmaf(s[nt][1], scale2, -SM_SHIFT));
            float p2 = ex2(fmaf(s[nt][2], scale2, -SM_SHIFT));
            float p3 = ex2(fmaf(s[nt][3], scale2, -SM_SHIFT));
            lp[0] += p0 + p1; lp[1] += p2 + p3;
            split2(p0, p1, Ph0[nt], Pl0[nt]);
            split2(p2, p3, Ph1[nt], Pl1[nt]);
        }

        // ---- O += P V: ksj-outer, rotate over 6 accumulators per term
        #pragma unroll
        for (int ksj = 0; ksj < 4; ksj++) {
            unsigned vh0[6], vh1[6], vl0[6], vl1[6];
            #pragma unroll
            for (int nt2 = 0; nt2 < 6; nt2++) {
                const __nv_bfloat16* vrh = Vh + (nt2*8 + g)*72 + ksj*16 + 2*tig;
                const __nv_bfloat16* vrl = Vl + (nt2*8 + g)*72 + ksj*16 + 2*tig;
                vh0[nt2] = *(const unsigned*)(vrh);
                vh1[nt2] = *(const unsigned*)(vrh + 8);
                vl0[nt2] = *(const unsigned*)(vrl);
                vl1[nt2] = *(const unsigned*)(vrl + 8);
            }
            unsigned Ahi[4] = {Ph0[2*ksj], Ph1[2*ksj], Ph0[2*ksj+1], Ph1[2*ksj+1]};
            unsigned Alo[4] = {Pl0[2*ksj], Pl1[2*ksj], Pl0[2*ksj+1], Pl1[2*ksj+1]};
            #pragma unroll
            for (int nt2 = 0; nt2 < 6; nt2++) mma16816(o[nt2], Ahi, vh0[nt2], vh1[nt2]);
            #pragma unroll
            for (int nt2 = 0; nt2 < 6; nt2++) mma16816(o[nt2], Ahi, vl0[nt2], vl1[nt2]);
            #pragma unroll
            for (int nt2 = 0; nt2 < 6; nt2++) mma16816(o[nt2], Alo, vh0[nt2], vh1[nt2]);
        }
        __syncthreads();
    }

    #pragma unroll
    for (int off = 1; off <= 2; off <<= 1) {
        lp[0] += __shfl_xor_sync(0xffffffffu, lp[0], off);
        lp[1] += __shfl_xor_sync(0xffffffffu, lp[1], off);
    }
    float inv0 = 1.f / lp[0], inv1 = 1.f / lp[1];
    size_t base0 = ((size_t)(b*NTOK + m0 + g    ))*DIMC + h*DEPTH;
    size_t base1 = ((size_t)(b*NTOK + m0 + g + 8))*DIMC + h*DEPTH;
    #pragma unroll
    for (int nt2 = 0; nt2 < 6; nt2++) {
        unsigned hi0, lo0, hi1, lo1;
        split2(o[nt2][0]*inv0, o[nt2][1]*inv0, hi0, lo0);
        split2(o[nt2][2]*inv1, o[nt2][3]*inv1, hi1, lo1);
        int co = nt2*8 + 2*tig;
        *(unsigned*)(g_ah + base0 + co) = hi0;
        *(unsigned*)(g_al + base0 + co) = lo0;
        *(unsigned*)(g_ah + base1 + co) = hi1;
        *(unsigned*)(g_al + base1 + co) = lo1;
    }
}

// ---------------------------------------------------------------------------
// 4) Output projection + bias; smem-transposed coalesced [B,C,N] writes.
// ---------------------------------------------------------------------------
__global__ void __launch_bounds__(256) out_mma(const float* __restrict__ bias,
                                               float* __restrict__ out) {
    extern __shared__ char dsm[];
    int m0 = blockIdx.y * 128, d0 = blockIdx.x * 64;
    int tid = threadIdx.x, w = tid >> 5, lane = tid & 31;
    int g = lane >> 2, tig = lane & 3;
    int mw = w >> 1, nw = w & 1;

    float acc[2][4][4] = {};
    gemm_mainloop(dsm,
        (const unsigned*)g_ah + (size_t)m0*192, (const unsigned*)g_al + (size_t)m0*192,
        (const unsigned*)g_woh + (size_t)d0*192, (const unsigned*)g_wol + (size_t)d0*192,
        tid, mw, nw, g, tig, acc);

    int bb = m0 / NTOK, n0 = m0 - bb*NTOK;
    __syncthreads();
    float* fb = (float*)dsm;                 // [128][65]
    #pragma unroll
    for (int mi = 0; mi < 2; mi++)
        #pragma unroll
        for (int rr = 0; rr < 2; rr++) {
            int ml = mw*32 + mi*16 + g + rr*8;
            #pragma unroll
            for (int ni = 0; ni < 4; ni++)
                #pragma unroll
                for (int jj = 0; jj < 2; jj++) {
                    int dl = nw*32 + ni*8 + 2*tig + jj;
                    fb[ml*65 + dl] = acc[mi][ni][rr*2 + jj] + bias[d0 + dl];
                }
        }
    __syncthreads();
    #pragma unroll
    for (int i = tid; i < 64*128; i += 256) {
        int dl = i >> 7, n = i & 127;
        out[((size_t)bb*DIMC + d0 + dl)*NTOK + n0 + n] = fb[n*65 + dl];
    }
}

// ---------------------------------------------------------------------------
extern "C" void kernel_launch(void* const* d_in, const int* in_sizes, int n_in,
                              void* d_out, int out_size) {
    const float* feat  = (const float*)d_in[0];
    const float* gamma = (const float*)d_in[1];
    const float* beta  = (const float*)d_in[2];
    const float* tau   = (const float*)d_in[3];
    const float* w_qkv = (const float*)d_in[4];
    const float* w_out = (const float*)d_in[5];
    const float* b_out = (const float*)d_in[6];
    float* out = (float*)d_out;

    static int smem_set = 0;
    if (!smem_set) {
        cudaFuncSetAttribute(attn_mma, cudaFuncAttributeMaxDynamicSharedMemorySize, 2*ST_SZ);
        cudaFuncSetAttribute(qkv_mma, cudaFuncAttributeMaxDynamicSharedMemorySize, G_SMEM);
        cudaFuncSetAttribute(out_mma, cudaFuncAttributeMaxDynamicSharedMemorySize, G_SMEM);
        smem_set = 1;
    }

    split_w<<<(QKVD*DIMC + 255)/256, 256>>>(w_qkv, w_out);
    ln_kernel<<<dim3(NTOK/64, BATCH), 256>>>(feat, gamma, beta);
    qkv_mma<<<dim3(QKVD/64, BATCH*NTOK/128), 256, G_SMEM>>>();
    attn_mma<<<dim3(NTOK/128, NHEAD, BATCH), 256, 2*ST_SZ>>>(tau);
    out_mma<<<dim3(DIMC/64, BATCH*NTOK/128), 256, G_SMEM>>>(b_out, out);
}